// round 14
// baseline (speedup 1.0000x reference)
#include <cuda_runtime.h>

// Problem constants
#define NB    512       // batch B
#define NMF   256       // M features
#define INDIM 50
#define SROW  51        // padded S row (conflict-free smem)
#define OFF_U 512
#define OFF_S 25088     // 512 + 512*48
#define OFF_W 37888     // OFF_S + 256*50
#define G     4         // batch elements per fwd block
#define NBLK  (NB/G)    // 128 fwd blocks (<= 148 SMs: all co-resident, spin is safe)
#define PART  13312     // per-block partial: 50*256 (grad_S, j-major) + 256 gc + 256 gs
#define QPB   26        // output quads per block in fused stage 2 (128*26*4 = 13312)

__device__ float g_part[NBLK * PART];
__device__ unsigned g_sync;

__device__ __forceinline__ float warp_sum(float v) {
#pragma unroll
    for (int o = 16; o; o >>= 1) v += __shfl_down_sync(0xffffffffu, v, o);
    return v;
}
__device__ __forceinline__ float xor_sum(float v) {
#pragma unroll
    for (int o = 16; o; o >>= 1) v += __shfl_xor_sync(0xffffffffu, v, o);
    return v;
}
// Named barrier over one 256-thread half (ids 1 and 2)
#define BAR_HALF(h) asm volatile("bar.sync %0, 256;" :: "r"(1 + (h)) : "memory")

// smem floats: S[256*51] | inp[4*64] | red[4*64+16] | e4[4*256] | et/ex/gc/gs [2*256]
#define SMEM_FLOATS (NMF*SROW + 256 + 272 + 1024 + 4*512)

// 512 threads: half = t>>8 handles g in {2*half, 2*half+1}; m = t & 255.
__global__ __launch_bounds__(512) void fwd_kernel(
    const float* __restrict__ U0, const float* __restrict__ U1,
    const float* __restrict__ U2, const float* __restrict__ S,
    const float* __restrict__ w,  const float* __restrict__ tn,
    const float* __restrict__ obs, const int* __restrict__ idx,
    float* __restrict__ out)
{
    extern __shared__ float sm[];
    float* Ssm   = sm;                    // 256*51 = 13056
    float* inp   = Ssm + NMF*SROW;        // 256
    float* red   = inp + 256;             // 272 ; [256..259] = lamA per g
    float* e4f   = red + 272;             // 1024: e packed [m][g]  (16B-aligned)
    float* et_sm = e4f + 1024;            // [half][256]
    float* ex_sm = et_sm + 512;
    float* gc_sm = ex_sm + 512;
    float* gs_sm = gc_sm + 512;
    float4* e4   = (float4*)e4f;

    const int b0   = blockIdx.x * G;
    const int t    = threadIdx.x;
    const int lane = t & 31;
    const int wid  = t >> 5;             // 0..15
    const int m    = t & 255;
    const int half = t >> 8;             // 0 or 1
    const int w8   = wid & 7;
    const int g0   = half * 2;

    // Load S via float4, scatter into padded smem rows
    {
        const float4* S4 = (const float4*)S;
        for (int i = t; i < (NMF*INDIM)/4; i += 512) {
            float4 v = S4[i];
            int base = i * 4;
#pragma unroll
            for (int c = 0; c < 4; c++) {
                int id = base + c;
                int mm = id / INDIM;
                int jj = id - mm*INDIM;
                float vc = (c == 0) ? v.x : (c == 1) ? v.y : (c == 2) ? v.z : v.w;
                Ssm[mm*SROW + jj] = vc;
            }
        }
    }
    // Gather Uvec (4 b x 48 values)
    if (t < G*48) {
        int gg = t / 48, j = t - gg*48;
        int v = j >> 4, r = j & 15;
        int iv = idx[(b0 + gg)*3 + v];
        const float* Uv = (v == 0) ? U0 : (v == 1) ? U1 : U2;
        inp[gg*64 + 2 + j] = Uv[iv*16 + r];
    }
    __syncthreads();

    const float wc = w[m], ws = w[256 + m];
    const float s0 = Ssm[m*SROW + 0], s1 = Ssm[m*SROW + 1];

    float scaleT[2], obsg[2], beta[2], phiU[2];
#pragma unroll
    for (int gi = 0; gi < 2; gi++) {
        const int g = g0 + gi;
        scaleT[gi] = tn[b0 + g];
        obsg[gi]   = obs[b0 + g];
        const float* inpg = inp + g*64;
        float bt = 0.f;
        if (lane < 16) bt = inpg[2 + lane] * inpg[18 + lane] * inpg[34 + lane];
        beta[gi] = xor_sum(bt);
    }
    // phi constant part: one Ssm read feeds both g's
    {
        float a0 = 0.f, a1 = 0.f;
        const float* i0 = inp + g0*64;
        const float* i1 = inp + (g0 + 1)*64;
#pragma unroll
        for (int j = 2; j < INDIM; j++) {
            float sv = Ssm[m*SROW + j];
            a0 = fmaf(sv, i0[j], a0);
            a1 = fmaf(sv, i1[j], a1);
        }
        phiU[0] = a0; phiU[1] = a1;
    }

    // ---- RK4 stages (t = 0, 0.5, 0.5, 1 ; h = 1), state in registers ----
    float in0[2] = {0.f, 0.f};
    float in1[2] = {beta[0], beta[1]};
    float cpS[4][2], spS[4][2], kS[4][2], JS[4][2], xS[4][2], tS[4][2];
#pragma unroll
    for (int i = 0; i < 4; i++) {
        float fp[2], jp[2];
#pragma unroll
        for (int gi = 0; gi < 2; gi++) {
            xS[i][gi] = in1[gi]; tS[i][gi] = in0[gi];
            float phi = phiU[gi] + s0*in0[gi] + s1*in1[gi];
            float cp, sp;
            __sincosf(phi, &sp, &cp);
            cpS[i][gi] = cp; spS[i][gi] = sp;
            fp[gi] = xor_sum(cp*wc + sp*ws);
            jp[gi] = xor_sum((cp*ws - sp*wc) * s1);
        }
        if (lane == 0) {
#pragma unroll
            for (int gi = 0; gi < 2; gi++) {
                const int g = g0 + gi;
                red[i*64 + g*8 + w8]      = fp[gi];
                red[i*64 + 32 + g*8 + w8] = jp[gi];
            }
        }
        BAR_HALF(half);
#pragma unroll
        for (int gi = 0; gi < 2; gi++) {
            const int g = g0 + gi;
            const float4* rf = (const float4*)(red + i*64 + g*8);
            const float4* rj = (const float4*)(red + i*64 + 32 + g*8);
            float4 f0 = rf[0], f1 = rf[1], j0 = rj[0], j1 = rj[1];
            float F  = ((f0.x + f0.y) + (f0.z + f0.w)) + ((f1.x + f1.y) + (f1.z + f1.w));
            float JJ = ((j0.x + j0.y) + (j0.z + j0.w)) + ((j1.x + j1.y) + (j1.z + j1.w));
            float k = scaleT[gi] * F;
            kS[i][gi] = k; JS[i][gi] = scaleT[gi] * JJ;
            if (i < 2)      { in1[gi] = beta[gi] + 0.5f*k; in0[gi] = scaleT[gi]*0.5f; }
            else if (i == 2){ in1[gi] = beta[gi] + k;      in0[gi] = scaleT[gi]; }
        }
    }

    // Discrete-adjoint RK4 coefficients + pass 2 (registers only)
    float eP[2];
    float etP = 0.f, exP = 0.f, gcP = 0.f, gsP = 0.f;
#pragma unroll
    for (int gi = 0; gi < 2; gi++) {
        const int g = g0 + gi;
        const float J1 = JS[0][gi], J2 = JS[1][gi], J3 = JS[2][gi], J4 = JS[3][gi];
        const float xT  = beta[gi] + (kS[0][gi] + 2.f*kS[1][gi] + 2.f*kS[2][gi] + kS[3][gi]) * (1.f/6.f);
        const float lam = (xT - obsg[gi]) * (1.f/512.f);
        const float a1 = J1;
        const float a2 = J2*(1.f + 0.5f*a1);
        const float a3 = J3*(1.f + 0.5f*a2);
        const float a4 = J4*(1.f + a3);
        const float A  = 1.f + (a1 + 2.f*a2 + 2.f*a3 + a4) * (1.f/6.f);
        const float ls = lam * scaleT[gi];
        float ch[4];
        ch[0] = ls * (1.f + J2 + 0.5f*J3*J2 + 0.25f*J4*J3*J2) * (1.f/6.f);
        ch[1] = ls * (2.f + J3 + 0.5f*J4*J3) * (1.f/6.f);
        ch[2] = ls * (2.f + J4) * (1.f/6.f);
        ch[3] = ls * (1.f/6.f);
        const float lamA = lam * A;
        if (m == 0) {
            out[b0 + g] = lamA;          // grad wrt beta (diagonal)
            red[256 + g] = lamA;
        }
        float e = 0.f;
#pragma unroll
        for (int i = 0; i < 4; i++) {
            float d  = cpS[i][gi]*ws - spS[i][gi]*wc;
            float cd = ch[i] * d;
            e   += cd;
            etP += cd * tS[i][gi];
            exP += cd * xS[i][gi];
            gcP += ch[i] * cpS[i][gi];
            gsP += ch[i] * spS[i][gi];
        }
        eP[gi] = e;
    }
    *(float2*)&e4f[m*4 + g0] = make_float2(eP[0], eP[1]);
    et_sm[half*256 + m] = etP;
    ex_sm[half*256 + m] = exP;
    gc_sm[half*256 + m] = gcP;
    gs_sm[half*256 + m] = gsP;
    __syncthreads();

    // ---- per-block partial grad_S (j-major) + grad_w -> g_part ----
    {
        const long bp = (long)blockIdx.x * PART;
        const float4 ev = e4[m];
        const float eg0 = ev.x, eg1 = ev.y, eg2 = ev.z, eg3 = ev.w;
        if (half == 0) {
            g_part[bp + 0*256 + m] = et_sm[m] + et_sm[256 + m];
            g_part[bp + 1*256 + m] = ex_sm[m] + ex_sm[256 + m];
#pragma unroll
            for (int c = 2; c < 25; c++) {
                float s = eg0*inp[c] + eg1*inp[64+c] + eg2*inp[128+c] + eg3*inp[192+c];
                g_part[bp + c*256 + m] = s;
            }
            g_part[bp + 12800 + m] = gc_sm[m] + gc_sm[256 + m];
        } else {
#pragma unroll
            for (int c = 25; c < 50; c++) {
                float s = eg0*inp[c] + eg1*inp[64+c] + eg2*inp[128+c] + eg3*inp[192+c];
                g_part[bp + c*256 + m] = s;
            }
            g_part[bp + 13056 + m] = gs_sm[m] + gs_sm[256 + m];
        }
    }

    // ---- grid barrier: release our partials, arrive (one RMW per block) ----
    __threadfence();
    __syncthreads();
    if (t == 0) atomicAdd(&g_sync, 1u);

    // ---- per-b Uvec gradient (independent of g_part -> overlaps other blocks' arrival)
#pragma unroll
    for (int q = 0; q < 3; q++) {
        const int j = wid*3 + q;
        float a0 = 0.f, a1 = 0.f, a2 = 0.f, a3 = 0.f;
#pragma unroll
        for (int k = 0; k < 8; k++) {
            int mm = lane + 32*k;
            float sv = Ssm[mm*SROW + 2 + j];
            float4 ev = e4[mm];
            a0 = fmaf(sv, ev.x, a0);
            a1 = fmaf(sv, ev.y, a1);
            a2 = fmaf(sv, ev.z, a2);
            a3 = fmaf(sv, ev.w, a3);
        }
        a0 = warp_sum(a0); a1 = warp_sum(a1); a2 = warp_sum(a2); a3 = warp_sum(a3);
        if (lane == 0) {
            const int v = j >> 4, r = j & 15;
            const float acc[4] = {a0, a1, a2, a3};
#pragma unroll
            for (int g = 0; g < 4; g++) {
                const float* inpg = inp + g*64;
                float u0 = inpg[2 + r], u1 = inpg[18 + r], u2 = inpg[34 + r];
                float pe = (v == 0) ? u1*u2 : (v == 1) ? u0*u2 : u0*u1;
                out[OFF_U + (b0 + g)*48 + j] = acc[g] + red[256 + g] * pe;
            }
        }
    }

    // ---- spin: volatile poll + nanosleep (NO atomic RMW on the hot address) ----
    if (t == 0) {
        const volatile unsigned* p = &g_sync;
        while (*p < (unsigned)NBLK) { __nanosleep(64); }
        __threadfence();   // acquire: order subsequent g_part reads after observation
    }
    __syncthreads();

    // ---- fused stage 2: this block reduces output quads [bid*26, bid*26+26) ----
    {
        const int ql = t & 31;           // quad lane (26 used)
        const int pg = t >> 5;           // 0..15 p-group (8 partials each)
        float4 a = make_float4(0.f, 0.f, 0.f, 0.f);
        if (ql < QPB) {
            const int q = blockIdx.x * QPB + ql;
            const float* P = g_part + 4*q;
#pragma unroll
            for (int k = 0; k < 8; k++) {
                float4 v = *(const float4*)(P + (long)(pg*8 + k)*PART);
                a.x += v.x; a.y += v.y; a.z += v.z; a.w += v.w;
            }
        }
        float4* rbuf = (float4*)sm;      // reuse Ssm region: [16][32] float4 = 8 KB
        rbuf[pg*32 + ql] = a;
        __syncthreads();
        if (t < QPB) {
            float4 s = rbuf[t];
#pragma unroll
            for (int k = 1; k < 16; k++) {
                float4 v = rbuf[k*32 + t];
                s.x += v.x; s.y += v.y; s.z += v.z; s.w += v.w;
            }
            const int Qo = blockIdx.x * QPB + t;
            const float sv[4] = {s.x, s.y, s.z, s.w};
#pragma unroll
            for (int c4 = 0; c4 < 4; c4++) {
                int i = 4*Qo + c4;
                if (i < 12800) {
                    int c = i >> 8, mm = i & 255;
                    out[OFF_S + mm*INDIM + c] = sv[c4];
                } else if (i < 13056) {
                    out[OFF_W + (i - 12800)] = sv[c4];
                } else {
                    out[OFF_W + 256 + (i - 13056)] = sv[c4];
                }
            }
        }
    }
}

extern "C" void kernel_launch(void* const* d_in, const int* in_sizes, int n_in,
                              void* d_out, int out_size)
{
    const float* U0  = (const float*)d_in[0];
    const float* U1  = (const float*)d_in[1];
    const float* U2  = (const float*)d_in[2];
    const float* S   = (const float*)d_in[3];
    const float* w   = (const float*)d_in[4];
    const float* tn  = (const float*)d_in[5];
    const float* obs = (const float*)d_in[6];
    const int*   idx = (const int*)d_in[7];
    float* out = (float*)d_out;

    void* syncAddr = nullptr;
    cudaGetSymbolAddress(&syncAddr, g_sync);
    cudaMemsetAsync(syncAddr, 0, sizeof(unsigned));

    const int smem_bytes = SMEM_FLOATS * (int)sizeof(float);
    cudaFuncSetAttribute(fwd_kernel, cudaFuncAttributeMaxDynamicSharedMemorySize, smem_bytes);

    fwd_kernel<<<NBLK, 512, smem_bytes>>>(U0, U1, U2, S, w, tn, obs, idx, out);
}

// round 15
// speedup vs baseline: 1.1074x; 1.1074x over previous
#include <cuda_runtime.h>

// Problem constants
#define NB    512       // batch B
#define NMF   256       // M features
#define INDIM 50
#define SROW  51        // padded S row (conflict-free smem)
#define OFF_U 512
#define OFF_S 25088     // 512 + 512*48
#define OFF_W 37888     // OFF_S + 256*50
#define G     4         // batch elements per fwd block
#define NBLK  (NB/G)    // 128 fwd blocks
#define PART  13312     // per-block partial: 50*256 (grad_S, j-major) + 256 gc + 256 gs

__device__ float g_part[NBLK * PART];

__device__ __forceinline__ float warp_sum(float v) {
#pragma unroll
    for (int o = 16; o; o >>= 1) v += __shfl_down_sync(0xffffffffu, v, o);
    return v;
}
__device__ __forceinline__ float xor_sum(float v) {
#pragma unroll
    for (int o = 16; o; o >>= 1) v += __shfl_xor_sync(0xffffffffu, v, o);
    return v;
}
// Named barrier over one 256-thread half (ids 1 and 2)
#define BAR_HALF(h) asm volatile("bar.sync %0, 256;" :: "r"(1 + (h)) : "memory")

// smem floats: S[256*51] | inp[4*64] | red[4*64+16] | e4[4*256] | et/ex/gc/gs [2*256]
#define SMEM_FLOATS (NMF*SROW + 256 + 272 + 1024 + 4*512)

// 512 threads: half = t>>8 handles g in {2*half, 2*half+1}; m = t & 255.
__global__ __launch_bounds__(512) void fwd_kernel(
    const float* __restrict__ U0, const float* __restrict__ U1,
    const float* __restrict__ U2, const float* __restrict__ S,
    const float* __restrict__ w,  const float* __restrict__ tn,
    const float* __restrict__ obs, const int* __restrict__ idx,
    float* __restrict__ out)
{
    extern __shared__ float sm[];
    float* Ssm   = sm;                    // 256*51 = 13056
    float* inp   = Ssm + NMF*SROW;        // 256
    float* red   = inp + 256;             // 272 ; [256..259] = lamA per g
    float* e4f   = red + 272;             // 1024: e packed [m][g]  (16B-aligned)
    float* et_sm = e4f + 1024;            // [half][256]
    float* ex_sm = et_sm + 512;
    float* gc_sm = ex_sm + 512;
    float* gs_sm = gc_sm + 512;
    float4* e4   = (float4*)e4f;

    const int b0   = blockIdx.x * G;
    const int t    = threadIdx.x;
    const int lane = t & 31;
    const int wid  = t >> 5;             // 0..15
    const int m    = t & 255;
    const int half = t >> 8;             // 0 or 1
    const int w8   = wid & 7;
    const int g0   = half * 2;

    // Load S via float4, scatter into padded smem rows
    {
        const float4* S4 = (const float4*)S;
        for (int i = t; i < (NMF*INDIM)/4; i += 512) {
            float4 v = S4[i];
            int base = i * 4;
#pragma unroll
            for (int c = 0; c < 4; c++) {
                int id = base + c;
                int mm = id / INDIM;
                int jj = id - mm*INDIM;
                float vc = (c == 0) ? v.x : (c == 1) ? v.y : (c == 2) ? v.z : v.w;
                Ssm[mm*SROW + jj] = vc;
            }
        }
    }
    // Gather Uvec (4 b x 48 values)
    if (t < G*48) {
        int gg = t / 48, j = t - gg*48;
        int v = j >> 4, r = j & 15;
        int iv = idx[(b0 + gg)*3 + v];
        const float* Uv = (v == 0) ? U0 : (v == 1) ? U1 : U2;
        inp[gg*64 + 2 + j] = Uv[iv*16 + r];
    }
    __syncthreads();

    const float wc = w[m], ws = w[256 + m];
    const float s0 = Ssm[m*SROW + 0], s1 = Ssm[m*SROW + 1];

    float scaleT[2], obsg[2], beta[2], phiU[2];
#pragma unroll
    for (int gi = 0; gi < 2; gi++) {
        const int g = g0 + gi;
        scaleT[gi] = tn[b0 + g];
        obsg[gi]   = obs[b0 + g];
        const float* inpg = inp + g*64;
        float bt = 0.f;
        if (lane < 16) bt = inpg[2 + lane] * inpg[18 + lane] * inpg[34 + lane];
        beta[gi] = xor_sum(bt);
    }
    // phi constant part: one Ssm read feeds both g's
    {
        float a0 = 0.f, a1 = 0.f;
        const float* i0 = inp + g0*64;
        const float* i1 = inp + (g0 + 1)*64;
#pragma unroll
        for (int j = 2; j < INDIM; j++) {
            float sv = Ssm[m*SROW + j];
            a0 = fmaf(sv, i0[j], a0);
            a1 = fmaf(sv, i1[j], a1);
        }
        phiU[0] = a0; phiU[1] = a1;
    }

    // ---- RK4 stages (t = 0, 0.5, 0.5, 1 ; h = 1), state in registers ----
    float in0[2] = {0.f, 0.f};
    float in1[2] = {beta[0], beta[1]};
    float cpS[4][2], spS[4][2], kS[4][2], JS[4][2], xS[4][2], tS[4][2];
#pragma unroll
    for (int i = 0; i < 4; i++) {
        float fp[2], jp[2];
#pragma unroll
        for (int gi = 0; gi < 2; gi++) {
            xS[i][gi] = in1[gi]; tS[i][gi] = in0[gi];
            float phi = phiU[gi] + s0*in0[gi] + s1*in1[gi];
            float cp, sp;
            __sincosf(phi, &sp, &cp);
            cpS[i][gi] = cp; spS[i][gi] = sp;
            fp[gi] = xor_sum(cp*wc + sp*ws);
            jp[gi] = xor_sum((cp*ws - sp*wc) * s1);
        }
        if (lane == 0) {
#pragma unroll
            for (int gi = 0; gi < 2; gi++) {
                const int g = g0 + gi;
                red[i*64 + g*8 + w8]      = fp[gi];
                red[i*64 + 32 + g*8 + w8] = jp[gi];
            }
        }
        BAR_HALF(half);
#pragma unroll
        for (int gi = 0; gi < 2; gi++) {
            const int g = g0 + gi;
            const float4* rf = (const float4*)(red + i*64 + g*8);
            const float4* rj = (const float4*)(red + i*64 + 32 + g*8);
            float4 f0 = rf[0], f1 = rf[1], j0 = rj[0], j1 = rj[1];
            float F  = ((f0.x + f0.y) + (f0.z + f0.w)) + ((f1.x + f1.y) + (f1.z + f1.w));
            float JJ = ((j0.x + j0.y) + (j0.z + j0.w)) + ((j1.x + j1.y) + (j1.z + j1.w));
            float k = scaleT[gi] * F;
            kS[i][gi] = k; JS[i][gi] = scaleT[gi] * JJ;
            if (i < 2)      { in1[gi] = beta[gi] + 0.5f*k; in0[gi] = scaleT[gi]*0.5f; }
            else if (i == 2){ in1[gi] = beta[gi] + k;      in0[gi] = scaleT[gi]; }
        }
    }

    // Discrete-adjoint RK4 coefficients + pass 2 (registers only)
    float eP[2];
    float etP = 0.f, exP = 0.f, gcP = 0.f, gsP = 0.f;
#pragma unroll
    for (int gi = 0; gi < 2; gi++) {
        const int g = g0 + gi;
        const float J1 = JS[0][gi], J2 = JS[1][gi], J3 = JS[2][gi], J4 = JS[3][gi];
        const float xT  = beta[gi] + (kS[0][gi] + 2.f*kS[1][gi] + 2.f*kS[2][gi] + kS[3][gi]) * (1.f/6.f);
        const float lam = (xT - obsg[gi]) * (1.f/512.f);
        const float a1 = J1;
        const float a2 = J2*(1.f + 0.5f*a1);
        const float a3 = J3*(1.f + 0.5f*a2);
        const float a4 = J4*(1.f + a3);
        const float A  = 1.f + (a1 + 2.f*a2 + 2.f*a3 + a4) * (1.f/6.f);
        const float ls = lam * scaleT[gi];
        float ch[4];
        ch[0] = ls * (1.f + J2 + 0.5f*J3*J2 + 0.25f*J4*J3*J2) * (1.f/6.f);
        ch[1] = ls * (2.f + J3 + 0.5f*J4*J3) * (1.f/6.f);
        ch[2] = ls * (2.f + J4) * (1.f/6.f);
        ch[3] = ls * (1.f/6.f);
        const float lamA = lam * A;
        if (m == 0) {
            out[b0 + g] = lamA;          // grad wrt beta (diagonal)
            red[256 + g] = lamA;
        }
        float e = 0.f;
#pragma unroll
        for (int i = 0; i < 4; i++) {
            float d  = cpS[i][gi]*ws - spS[i][gi]*wc;
            float cd = ch[i] * d;
            e   += cd;
            etP += cd * tS[i][gi];
            exP += cd * xS[i][gi];
            gcP += ch[i] * cpS[i][gi];
            gsP += ch[i] * spS[i][gi];
        }
        eP[gi] = e;
    }
    *(float2*)&e4f[m*4 + g0] = make_float2(eP[0], eP[1]);
    et_sm[half*256 + m] = etP;
    ex_sm[half*256 + m] = exP;
    gc_sm[half*256 + m] = gcP;
    gs_sm[half*256 + m] = gsP;
    __syncthreads();

    // ---- per-block partial grad_S (j-major) + grad_w -> g_part (FIRST: feeds red2)
    {
        const long bp = (long)blockIdx.x * PART;
        const float4 ev = e4[m];
        const float eg0 = ev.x, eg1 = ev.y, eg2 = ev.z, eg3 = ev.w;
        if (half == 0) {
            g_part[bp + 0*256 + m] = et_sm[m] + et_sm[256 + m];
            g_part[bp + 1*256 + m] = ex_sm[m] + ex_sm[256 + m];
#pragma unroll
            for (int c = 2; c < 25; c++) {
                float s = eg0*inp[c] + eg1*inp[64+c] + eg2*inp[128+c] + eg3*inp[192+c];
                g_part[bp + c*256 + m] = s;
            }
            g_part[bp + 12800 + m] = gc_sm[m] + gc_sm[256 + m];
        } else {
#pragma unroll
            for (int c = 25; c < 50; c++) {
                float s = eg0*inp[c] + eg1*inp[64+c] + eg2*inp[128+c] + eg3*inp[192+c];
                g_part[bp + c*256 + m] = s;
            }
            g_part[bp + 13056 + m] = gs_sm[m] + gs_sm[256 + m];
        }
    }

    // ---- PDL trigger: partials published -> let red2 start spinning up ----
    __syncthreads();
    if (t == 0) {
        __threadfence();
#if __CUDA_ARCH__ >= 900
        cudaTriggerProgrammaticLaunchCompletion();
#endif
    }

    // ---- per-b Uvec gradient: task = j (48 tasks, 3/warp), all 4 g at once ----
    // (independent of g_part; overlaps red2's launch)
#pragma unroll
    for (int q = 0; q < 3; q++) {
        const int j = wid*3 + q;
        float a0 = 0.f, a1 = 0.f, a2 = 0.f, a3 = 0.f;
#pragma unroll
        for (int k = 0; k < 8; k++) {
            int mm = lane + 32*k;
            float sv = Ssm[mm*SROW + 2 + j];
            float4 ev = e4[mm];
            a0 = fmaf(sv, ev.x, a0);
            a1 = fmaf(sv, ev.y, a1);
            a2 = fmaf(sv, ev.z, a2);
            a3 = fmaf(sv, ev.w, a3);
        }
        a0 = warp_sum(a0); a1 = warp_sum(a1); a2 = warp_sum(a2); a3 = warp_sum(a3);
        if (lane == 0) {
            const int v = j >> 4, r = j & 15;
            const float acc[4] = {a0, a1, a2, a3};
#pragma unroll
            for (int g = 0; g < 4; g++) {
                const float* inpg = inp + g*64;
                float u0 = inpg[2 + r], u1 = inpg[18 + r], u2 = inpg[34 + r];
                float pe = (v == 0) ? u1*u2 : (v == 1) ? u0*u2 : u0*u1;
                out[OFF_U + (b0 + g)*48 + j] = acc[g] + red[256 + g] * pe;
            }
        }
    }
}

// Stage 2: sum 128 per-block partials for each of 13312 outputs.
// PDL secondary: waits on fwd's completion via cudaGridDependencySynchronize.
__global__ __launch_bounds__(256) void red2_kernel(float* __restrict__ out)
{
    __shared__ float4 redq[8][4];
    const int t  = threadIdx.x;
    const int pg = t >> 2;              // 0..63
    const int ql = t & 3;               // 0..3
    const int Q  = blockIdx.x * 4 + ql; // global output quad (0..3327)
    const float* P = g_part + 4*Q;
    const int p0 = pg * 2;
    const float* a0p = P + (long)(p0 + 0)*PART;
    const float* a1p = P + (long)(p0 + 1)*PART;

#if __CUDA_ARCH__ >= 900
    cudaGridDependencySynchronize();    // all fwd blocks done -> g_part complete
#endif

    float4 v0 = *(const float4*)a0p;
    float4 v1 = *(const float4*)a1p;
    float4 a;
    a.x = v0.x + v1.x;
    a.y = v0.y + v1.y;
    a.z = v0.z + v1.z;
    a.w = v0.w + v1.w;
#pragma unroll
    for (int mask = 4; mask <= 16; mask <<= 1) {
        a.x += __shfl_xor_sync(0xffffffffu, a.x, mask);
        a.y += __shfl_xor_sync(0xffffffffu, a.y, mask);
        a.z += __shfl_xor_sync(0xffffffffu, a.z, mask);
        a.w += __shfl_xor_sync(0xffffffffu, a.w, mask);
    }
    if ((t & 31) < 4) redq[t >> 5][t & 3] = a;
    __syncthreads();

    if (t < 4) {
        float4 s = redq[0][t];
#pragma unroll
        for (int ww = 1; ww < 8; ww++) {
            float4 v = redq[ww][t];
            s.x += v.x; s.y += v.y; s.z += v.z; s.w += v.w;
        }
        const int Qo = blockIdx.x * 4 + t;
        const float sv[4] = {s.x, s.y, s.z, s.w};
#pragma unroll
        for (int c4 = 0; c4 < 4; c4++) {
            int i = 4*Qo + c4;
            if (i < 12800) {
                int c = i >> 8, mm = i & 255;
                out[OFF_S + mm*INDIM + c] = sv[c4];
            } else if (i < 13056) {
                out[OFF_W + (i - 12800)] = sv[c4];
            } else {
                out[OFF_W + 256 + (i - 13056)] = sv[c4];
            }
        }
    }
}

extern "C" void kernel_launch(void* const* d_in, const int* in_sizes, int n_in,
                              void* d_out, int out_size)
{
    const float* U0  = (const float*)d_in[0];
    const float* U1  = (const float*)d_in[1];
    const float* U2  = (const float*)d_in[2];
    const float* S   = (const float*)d_in[3];
    const float* w   = (const float*)d_in[4];
    const float* tn  = (const float*)d_in[5];
    const float* obs = (const float*)d_in[6];
    const int*   idx = (const int*)d_in[7];
    float* out = (float*)d_out;

    const int smem_bytes = SMEM_FLOATS * (int)sizeof(float);
    cudaFuncSetAttribute(fwd_kernel, cudaFuncAttributeMaxDynamicSharedMemorySize, smem_bytes);

    fwd_kernel<<<NBLK, 512, smem_bytes>>>(U0, U1, U2, S, w, tn, obs, idx, out);

    // red2 as a PDL secondary: may begin launching while fwd drains; it gates
    // itself on cudaGridDependencySynchronize() before reading g_part.
    cudaLaunchConfig_t cfg = {};
    cfg.gridDim  = dim3(832, 1, 1);
    cfg.blockDim = dim3(256, 1, 1);
    cfg.dynamicSmemBytes = 0;
    cfg.stream = 0;
    cudaLaunchAttribute attrs[1];
    attrs[0].id = cudaLaunchAttributeProgrammaticStreamSerialization;
    attrs[0].val.programmaticStreamSerializationAllowed = 1;
    cfg.attrs = attrs;
    cfg.numAttrs = 1;
    cudaError_t err = cudaLaunchKernelEx(&cfg, red2_kernel, out);
    if (err != cudaSuccess) {
        // Fallback: plain serialized launch (still correct)
        red2_kernel<<<832, 256>>>(out);
    }
}

// round 16
// speedup vs baseline: 1.1678x; 1.0545x over previous
#include <cuda_runtime.h>

// Problem constants
#define NB    512       // batch B
#define NMF   256       // M features
#define INDIM 50
#define OFF_U 512
#define OFF_S 25088     // 512 + 512*48
#define OFF_W 37888     // OFF_S + 256*50
#define G     4         // batch elements per fwd block
#define NBLK  (NB/G)    // 128 fwd blocks
#define PART  13312     // per-block partial: 50*256 (grad_S, j-major) + 256 gc + 256 gs

__device__ float g_part[NBLK * PART];

__device__ __forceinline__ float warp_sum(float v) {
#pragma unroll
    for (int o = 16; o; o >>= 1) v += __shfl_down_sync(0xffffffffu, v, o);
    return v;
}
__device__ __forceinline__ float xor_sum(float v) {
#pragma unroll
    for (int o = 16; o; o >>= 1) v += __shfl_xor_sync(0xffffffffu, v, o);
    return v;
}
// Named barrier over one 256-thread half (ids 1 and 2)
#define BAR_HALF(h) asm volatile("bar.sync %0, 256;" :: "r"(1 + (h)) : "memory")

// smem floats: S[256*50 linear] | uvec inp[4*64] | red[272] | e4[1024] | et/ex/gc/gs [2*256]
#define SMEM_FLOATS (NMF*INDIM + 256 + 272 + 1024 + 4*512)

// 512 threads: half = t>>8 handles g in {2*half, 2*half+1}; m = t & 255.
// S stored LINEAR in smem (row m at Ssm + m*50). uvec at inp[g*64 + 0..47].
__global__ __launch_bounds__(512) void fwd_kernel(
    const float* __restrict__ U0, const float* __restrict__ U1,
    const float* __restrict__ U2, const float* __restrict__ S,
    const float* __restrict__ w,  const float* __restrict__ tn,
    const float* __restrict__ obs, const int* __restrict__ idx,
    float* __restrict__ out)
{
    extern __shared__ float sm[];
    float* Ssm   = sm;                    // 256*50 = 12800 (linear)
    float* inp   = Ssm + NMF*INDIM;       // 256 (uvec only)
    float* red   = inp + 256;             // 272 ; [256..259] = lamA per g
    float* e4f   = red + 272;             // 1024: e packed [m][g]  (16B-aligned)
    float* et_sm = e4f + 1024;            // [half][256]
    float* ex_sm = et_sm + 512;
    float* gc_sm = ex_sm + 512;
    float* gs_sm = gc_sm + 512;
    float4* e4   = (float4*)e4f;

    const int b0   = blockIdx.x * G;
    const int t    = threadIdx.x;
    const int lane = t & 31;
    const int wid  = t >> 5;             // 0..15
    const int m    = t & 255;
    const int half = t >> 8;             // 0 or 1
    const int w8   = wid & 7;
    const int g0   = half * 2;

    // Load S: straight float4 memcpy into linear smem (no index math)
    {
        const float4* S4 = (const float4*)S;
        float4* Ssm4 = (float4*)Ssm;
#pragma unroll
        for (int r = 0; r < 7; r++) {
            int i = t + 512*r;
            if (i < (NMF*INDIM)/4) Ssm4[i] = S4[i];
        }
    }
    // Gather Uvec (4 b x 48 values) at inp[g*64 + v*16 + r]
    if (t < G*48) {
        int gg = t / 48, j = t - gg*48;
        int v = j >> 4, r = j & 15;
        int iv = idx[(b0 + gg)*3 + v];
        const float* Uv = (v == 0) ? U0 : (v == 1) ? U1 : U2;
        inp[gg*64 + j] = Uv[iv*16 + r];
    }
    __syncthreads();

    const float wc = w[m], ws = w[256 + m];
    const float2* Srow2 = (const float2*)(Ssm + m*INDIM);   // 50m even -> 8B aligned
    const float2 s01 = Srow2[0];
    const float s0 = s01.x, s1 = s01.y;

    float scaleT[2], obsg[2], beta[2], phiU[2];
#pragma unroll
    for (int gi = 0; gi < 2; gi++) {
        const int g = g0 + gi;
        scaleT[gi] = tn[b0 + g];
        obsg[gi]   = obs[b0 + g];
        const float* inpg = inp + g*64;
        float bt = 0.f;
        if (lane < 16) bt = inpg[lane] * inpg[16 + lane] * inpg[32 + lane];
        beta[gi] = xor_sum(bt);
    }
    // phi constant part: S row via float2 (2-way conflict), inp via float2 broadcast
    {
        float a0 = 0.f, a1 = 0.f;
        const float2* i0q = (const float2*)(inp + g0*64);
        const float2* i1q = (const float2*)(inp + g0*64 + 64);
#pragma unroll
        for (int q = 0; q < 24; q++) {
            float2 sv = Srow2[1 + q];      // S[m][2+2q], S[m][3+2q]
            float2 x0 = i0q[q];            // uvec[2q], uvec[2q+1]
            float2 x1 = i1q[q];
            a0 = fmaf(sv.x, x0.x, a0); a0 = fmaf(sv.y, x0.y, a0);
            a1 = fmaf(sv.x, x1.x, a1); a1 = fmaf(sv.y, x1.y, a1);
        }
        phiU[0] = a0; phiU[1] = a1;
    }

    // ---- RK4 stages (t = 0, 0.5, 0.5, 1 ; h = 1), state in registers ----
    float in0[2] = {0.f, 0.f};
    float in1[2] = {beta[0], beta[1]};
    float cpS[4][2], spS[4][2], kS[4][2], JS[4][2], xS[4][2], tS[4][2];
#pragma unroll
    for (int i = 0; i < 4; i++) {
        float fp[2], jp[2];
#pragma unroll
        for (int gi = 0; gi < 2; gi++) {
            xS[i][gi] = in1[gi]; tS[i][gi] = in0[gi];
            float phi = phiU[gi] + s0*in0[gi] + s1*in1[gi];
            float cp, sp;
            __sincosf(phi, &sp, &cp);
            cpS[i][gi] = cp; spS[i][gi] = sp;
            fp[gi] = xor_sum(cp*wc + sp*ws);
            jp[gi] = xor_sum((cp*ws - sp*wc) * s1);
        }
        if (lane == 0) {
#pragma unroll
            for (int gi = 0; gi < 2; gi++) {
                const int g = g0 + gi;
                red[i*64 + g*8 + w8]      = fp[gi];
                red[i*64 + 32 + g*8 + w8] = jp[gi];
            }
        }
        BAR_HALF(half);
#pragma unroll
        for (int gi = 0; gi < 2; gi++) {
            const int g = g0 + gi;
            const float4* rf = (const float4*)(red + i*64 + g*8);
            const float4* rj = (const float4*)(red + i*64 + 32 + g*8);
            float4 f0 = rf[0], f1 = rf[1], j0 = rj[0], j1 = rj[1];
            float F  = ((f0.x + f0.y) + (f0.z + f0.w)) + ((f1.x + f1.y) + (f1.z + f1.w));
            float JJ = ((j0.x + j0.y) + (j0.z + j0.w)) + ((j1.x + j1.y) + (j1.z + j1.w));
            float k = scaleT[gi] * F;
            kS[i][gi] = k; JS[i][gi] = scaleT[gi] * JJ;
            if (i < 2)      { in1[gi] = beta[gi] + 0.5f*k; in0[gi] = scaleT[gi]*0.5f; }
            else if (i == 2){ in1[gi] = beta[gi] + k;      in0[gi] = scaleT[gi]; }
        }
    }

    // Discrete-adjoint RK4 coefficients + pass 2 (registers only)
    float eP[2];
    float etP = 0.f, exP = 0.f, gcP = 0.f, gsP = 0.f;
#pragma unroll
    for (int gi = 0; gi < 2; gi++) {
        const int g = g0 + gi;
        const float J1 = JS[0][gi], J2 = JS[1][gi], J3 = JS[2][gi], J4 = JS[3][gi];
        const float xT  = beta[gi] + (kS[0][gi] + 2.f*kS[1][gi] + 2.f*kS[2][gi] + kS[3][gi]) * (1.f/6.f);
        const float lam = (xT - obsg[gi]) * (1.f/512.f);
        const float a1 = J1;
        const float a2 = J2*(1.f + 0.5f*a1);
        const float a3 = J3*(1.f + 0.5f*a2);
        const float a4 = J4*(1.f + a3);
        const float A  = 1.f + (a1 + 2.f*a2 + 2.f*a3 + a4) * (1.f/6.f);
        const float ls = lam * scaleT[gi];
        float ch[4];
        ch[0] = ls * (1.f + J2 + 0.5f*J3*J2 + 0.25f*J4*J3*J2) * (1.f/6.f);
        ch[1] = ls * (2.f + J3 + 0.5f*J4*J3) * (1.f/6.f);
        ch[2] = ls * (2.f + J4) * (1.f/6.f);
        ch[3] = ls * (1.f/6.f);
        const float lamA = lam * A;
        if (m == 0) {
            out[b0 + g] = lamA;          // grad wrt beta (diagonal)
            red[256 + g] = lamA;
        }
        float e = 0.f;
#pragma unroll
        for (int i = 0; i < 4; i++) {
            float d  = cpS[i][gi]*ws - spS[i][gi]*wc;
            float cd = ch[i] * d;
            e   += cd;
            etP += cd * tS[i][gi];
            exP += cd * xS[i][gi];
            gcP += ch[i] * cpS[i][gi];
            gsP += ch[i] * spS[i][gi];
        }
        eP[gi] = e;
    }
    *(float2*)&e4f[m*4 + g0] = make_float2(eP[0], eP[1]);
    et_sm[half*256 + m] = etP;
    ex_sm[half*256 + m] = exP;
    gc_sm[half*256 + m] = gcP;
    gs_sm[half*256 + m] = gsP;
    __syncthreads();

    // ---- per-b Uvec gradient: task = j (48 tasks, 3/warp), all 4 g at once ----
#pragma unroll
    for (int q = 0; q < 3; q++) {
        const int j = wid*3 + q;
        float a0 = 0.f, a1 = 0.f, a2 = 0.f, a3 = 0.f;
#pragma unroll
        for (int k = 0; k < 8; k++) {
            int mm = lane + 32*k;
            float sv = Ssm[mm*INDIM + 2 + j];
            float4 ev = e4[mm];
            a0 = fmaf(sv, ev.x, a0);
            a1 = fmaf(sv, ev.y, a1);
            a2 = fmaf(sv, ev.z, a2);
            a3 = fmaf(sv, ev.w, a3);
        }
        a0 = warp_sum(a0); a1 = warp_sum(a1); a2 = warp_sum(a2); a3 = warp_sum(a3);
        if (lane == 0) {
            const int v = j >> 4, r = j & 15;
            const float acc[4] = {a0, a1, a2, a3};
#pragma unroll
            for (int g = 0; g < 4; g++) {
                const float* ing = inp + g*64;
                float u0 = ing[r], u1 = ing[16 + r], u2 = ing[32 + r];
                float pe = (v == 0) ? u1*u2 : (v == 1) ? u0*u2 : u0*u1;
                out[OFF_U + (b0 + g)*48 + j] = acc[g] + red[256 + g] * pe;
            }
        }
    }

    // ---- per-block partial grad_S (j-major) + grad_w, uvec via float4 quads ----
    {
        const long bp = (long)blockIdx.x * PART;
        const float4 ev = e4[m];
        const float4* u0q = (const float4*)(inp);
        const float4* u1q = (const float4*)(inp + 64);
        const float4* u2q = (const float4*)(inp + 128);
        const float4* u3q = (const float4*)(inp + 192);
        const int jq0 = half * 6, jq1 = jq0 + 6;   // half0: j 0..23 (c 2..25), half1: j 24..47
#pragma unroll
        for (int jq = jq0; jq < jq1; jq++) {
            float4 q0 = u0q[jq], q1 = u1q[jq], q2 = u2q[jq], q3 = u3q[jq];
            const int cb = 2 + 4*jq;
            g_part[bp + (cb+0)*256 + m] = ev.x*q0.x + ev.y*q1.x + ev.z*q2.x + ev.w*q3.x;
            g_part[bp + (cb+1)*256 + m] = ev.x*q0.y + ev.y*q1.y + ev.z*q2.y + ev.w*q3.y;
            g_part[bp + (cb+2)*256 + m] = ev.x*q0.z + ev.y*q1.z + ev.z*q2.z + ev.w*q3.z;
            g_part[bp + (cb+3)*256 + m] = ev.x*q0.w + ev.y*q1.w + ev.z*q2.w + ev.w*q3.w;
        }
        if (half == 0) {
            g_part[bp + 0*256 + m]  = et_sm[m] + et_sm[256 + m];
            g_part[bp + 1*256 + m]  = ex_sm[m] + ex_sm[256 + m];
        } else {
            g_part[bp + 12800 + m]  = gc_sm[m] + gc_sm[256 + m];
            g_part[bp + 13056 + m]  = gs_sm[m] + gs_sm[256 + m];
        }
    }
}

// Stage 2: sum 128 per-block partials for each of 13312 outputs.
// thread = (p-group pg of 64, quad ql of 4): sums 2 partials (2 x LDG.128),
// 3-level shfl_xor over the 8 p-groups in its warp, 8x4 smem tile, 4-thread tail.
__global__ __launch_bounds__(256) void red2_kernel(float* __restrict__ out)
{
    __shared__ float4 redq[8][4];
    const int t  = threadIdx.x;
    const int pg = t >> 2;              // 0..63
    const int ql = t & 3;               // 0..3
    const int Q  = blockIdx.x * 4 + ql; // global output quad (0..3327)
    const float* P = g_part + 4*Q;

    const int p0 = pg * 2;
    float4 v0 = *(const float4*)(P + (long)(p0 + 0)*PART);
    float4 v1 = *(const float4*)(P + (long)(p0 + 1)*PART);
    float4 a;
    a.x = v0.x + v1.x;
    a.y = v0.y + v1.y;
    a.z = v0.z + v1.z;
    a.w = v0.w + v1.w;
#pragma unroll
    for (int mask = 4; mask <= 16; mask <<= 1) {
        a.x += __shfl_xor_sync(0xffffffffu, a.x, mask);
        a.y += __shfl_xor_sync(0xffffffffu, a.y, mask);
        a.z += __shfl_xor_sync(0xffffffffu, a.z, mask);
        a.w += __shfl_xor_sync(0xffffffffu, a.w, mask);
    }
    if ((t & 31) < 4) redq[t >> 5][t & 3] = a;
    __syncthreads();

    if (t < 4) {
        float4 s = redq[0][t];
#pragma unroll
        for (int ww = 1; ww < 8; ww++) {
            float4 v = redq[ww][t];
            s.x += v.x; s.y += v.y; s.z += v.z; s.w += v.w;
        }
        const int Qo = blockIdx.x * 4 + t;
        const float sv[4] = {s.x, s.y, s.z, s.w};
#pragma unroll
        for (int c4 = 0; c4 < 4; c4++) {
            int i = 4*Qo + c4;
            if (i < 12800) {
                int c = i >> 8, mm = i & 255;
                out[OFF_S + mm*INDIM + c] = sv[c4];
            } else if (i < 13056) {
                out[OFF_W + (i - 12800)] = sv[c4];
            } else {
                out[OFF_W + 256 + (i - 13056)] = sv[c4];
            }
        }
    }
}

extern "C" void kernel_launch(void* const* d_in, const int* in_sizes, int n_in,
                              void* d_out, int out_size)
{
    const float* U0  = (const float*)d_in[0];
    const float* U1  = (const float*)d_in[1];
    const float* U2  = (const float*)d_in[2];
    const float* S   = (const float*)d_in[3];
    const float* w   = (const float*)d_in[4];
    const float* tn  = (const float*)d_in[5];
    const float* obs = (const float*)d_in[6];
    const int*   idx = (const int*)d_in[7];
    float* out = (float*)d_out;

    const int smem_bytes = SMEM_FLOATS * (int)sizeof(float);
    cudaFuncSetAttribute(fwd_kernel, cudaFuncAttributeMaxDynamicSharedMemorySize, smem_bytes);

    fwd_kernel<<<NBLK, 512, smem_bytes>>>(U0, U1, U2, S, w, tn, obs, idx, out);
    red2_kernel<<<832, 256>>>(out);
}